// round 13
// baseline (speedup 1.0000x reference)
#include <cuda_runtime.h>
#include <math.h>

#define MOBJ 36
#define OBJ  10
#define NPL  16
#define WARPS 8          // rows per block == warps per block
#define NITEM 55         // upper triangle incl. diagonal of 10x10
#define DPAD 12          // padded dedup column stride (floats)

#define PLMAGIC  12582912.0f   // 1.5 * 2^23
#define PLMAGICI 0x4B400000u

// floor(y) as small int + fractional part, no F2I/I2F/IMIN (y in [0,16]).
__device__ __forceinline__ void plfloor(float y, int& idx, float& f) {
    float z = __fadd_rd(y, PLMAGIC);
    idx = (int)(__float_as_uint(z) - PLMAGICI);
    f = y - (z - PLMAGIC);
}

__device__ __forceinline__ float plin2t(const float2* __restrict__ t, float y) {
    int idx; float f;
    plfloor(y, idx, f);
    float2 v = t[idx];
    return fmaf(f, v.y, v.x);
}

// replicated-table variant: baseL = &tab2r[0][lane], row stride 32 float2.
__device__ __forceinline__ float plin2r(const float2* __restrict__ baseL, float y) {
    int idx; float f;
    plfloor(y, idx, f);
    float2 v = baseL[idx * 32];
    return fmaf(f, v.y, v.x);
}

__device__ __forceinline__ float warp_sum(float v) {
#pragma unroll
    for (int o = 16; o; o >>= 1) v += __shfl_xor_sync(0xffffffffu, v, o);
    return v;
}

// monotone map float -> u32 (order preserving), and inverse
__device__ __forceinline__ unsigned mapf(float v) {
    unsigned u = __float_as_uint(v);
    return u ^ ((unsigned)(((int)u) >> 31) | 0x80000000u);
}
__device__ __forceinline__ float unmapf(unsigned m) {
    unsigned u = (m & 0x80000000u) ? (m ^ 0x80000000u) : ~m;
    return __uint_as_float(u);
}

__global__ __launch_bounds__(WARPS * 32, 8)
void counter_kernel(const float* __restrict__ boxes,
                    const float* __restrict__ attn,
                    const float* __restrict__ ws,
                    float* __restrict__ out, int n) {
    __shared__ float4 tabR[NPL + 1];     // {csum0, w0', csum3, w3'}
    __shared__ float4 tabD[NPL + 1];     // {csum1, w1', csum4, w4'}
    __shared__ float2 tabD6[NPL + 1];    // {csum6, w6'}
    __shared__ float2 tab2[NPL + 1], tab5[NPL + 1], tab7[NPL + 1];
    __shared__ float2 tab2r[NPL + 1][32];          // lane-replicated tab2
    __shared__ unsigned char s_pb[NITEM + 1], s_pc[NITEM + 1];
    __shared__ float  s_att[WARPS][OBJ];
    __shared__ float4 s_box[WARPS][OBJ];
    __shared__ __align__(16) float s_dT[WARPS][OBJ][DPAD];  // dedup, padded cols
    __shared__ float  s_sim[WARPS][OBJ * OBJ];
    __shared__ float  s_ri[WARPS][OBJ];
    __shared__ float  s_p0[WARPS][OBJ];

    const int tid = threadIdx.x;
    const int warp = tid >> 5, lane = tid & 31;

    // ---- normalize 8 weight sets into packed fused tables ----
    if (tid < 8) {
        float tmp[NPL + 1];
        float s = 0.0f;
#pragma unroll
        for (int k = 0; k <= NPL; k++) { tmp[k] = fabsf(ws[tid * (NPL + 1) + k]); s += tmp[k]; }
        float inv = 1.0f / s;
        float* bp; int st;
        switch (tid) {
            case 0: bp = &tabR[0].x;  st = 4; break;
            case 3: bp = &tabR[0].z;  st = 4; break;
            case 1: bp = &tabD[0].x;  st = 4; break;
            case 4: bp = &tabD[0].z;  st = 4; break;
            case 6: bp = &tabD6[0].x; st = 2; break;
            case 2: bp = &tab2[0].x;  st = 2; break;
            case 5: bp = &tab5[0].x;  st = 2; break;
            default: bp = &tab7[0].x; st = 2; break;
        }
        float c = 0.0f;
#pragma unroll
        for (int k = 0; k <= NPL; k++) {
            c += tmp[k] * inv;
            int k1 = (k + 1) < NPL ? (k + 1) : NPL;
            bp[k * st]     = c;
            bp[k * st + 1] = tmp[k1] * inv;
        }
    }
    // item map p -> (b,c), b <= c
    if (tid < NITEM) {
        int p = tid, b = 0;
        while (p >= OBJ - b) { p -= OBJ - b; b++; }
        s_pb[tid] = (unsigned char)b;
        s_pc[tid] = (unsigned char)(b + p);
    }
    __syncthreads();

    // ---- replicate tab2 across lanes (conflict-free hot lookups) ----
#pragma unroll
    for (int k = warp; k <= NPL; k += WARPS) tab2r[k][lane] = tab2[k];
    __syncthreads();

    const int row = blockIdx.x * WARPS + warp;
    if (row >= n) return;

    const float2* t2L = &tab2r[0][lane];

    // ---- warp top-10 of 36 via REDUX (exact, low-index tie-break) ----
    unsigned u0 = mapf(attn[row * MOBJ + lane]);
    unsigned u1 = 0;
    if (lane < MOBJ - 32) u1 = mapf(attn[row * MOBJ + 32 + lane]);
    unsigned myval = 0, myidx = 0;
#pragma unroll
    for (int k = 0; k < OBJ; k++) {
        unsigned cand = u0 > u1 ? u0 : u1;
        unsigned m = __reduce_max_sync(0xffffffffu, cand);
        unsigned idx = 0xFFFFFFFFu;
        if (u0 == m) idx = (unsigned)lane;
        if (u1 == m) idx = min(idx, (unsigned)(lane + 32));
        unsigned sel = __reduce_min_sync(0xffffffffu, idx);
        if (sel == (unsigned)lane) u0 = 0;
        else if (sel == (unsigned)(lane + 32)) u1 = 0;
        if (lane == k) { myval = m; myidx = sel; }
    }
    if (lane < OBJ) {
        float v = unmapf(myval);
        float a = __fdividef(1.0f, 1.0f + __expf(-v));
        s_att[warp][lane] = a;
        const float* bb = boxes + (size_t)row * 4 * MOBJ + myidx;
        s_box[warp][lane] = make_float4(bb[0], bb[MOBJ], bb[2 * MOBJ], bb[3 * MOBJ]);
    }
    __syncwarp();

    // ---- pair stage: 55 items (b<=c); shared floors, packed tables ----
    float dconf = 0.0f;
    float sc[2], dav[2];
    int pb[2], pc[2];
#pragma unroll
    for (int r = 0; r < 2; r++) {
        int p = lane + r * 32;
        sc[r] = 0.0f; dav[r] = 0.0f; pb[r] = 0; pc[r] = 0;
        if (p < NITEM) {
            int b = s_pb[p], c = s_pc[p];
            pb[r] = b; pc[r] = c;
            float4 B = s_box[warp][b], C = s_box[warp][c];
            float iw = fmaxf(fminf(B.z, C.z) - fmaxf(B.x, C.x), 0.0f);
            float ih = fmaxf(fminf(B.w, C.w) - fmaxf(B.y, C.y), 0.0f);
            float inter = iw * ih;
            float aa = fmaxf(B.z - B.x, 0.0f) * fmaxf(B.w - B.y, 0.0f);
            float ab = fmaxf(C.z - C.x, 0.0f) * fmaxf(C.w - C.y, 0.0f);
            float dist = fmaxf(1.0f - __fdividef(inter, aa + ab - inter + 1e-12f), 0.0f);
            float atb = s_att[warp][b], atc = s_att[warp][c];
            float relev = atb * atc;
            dav[r] = fabsf(atb - atc);
            int ir; float fr; plfloor(16.0f * relev, ir, fr);
            float4 R = tabR[ir];
            float p0 = fmaf(fr, R.y, R.x);
            float p3 = fmaf(fr, R.w, R.z);
            int id; float fd; plfloor(16.0f * dist, id, fd);
            float4 D = tabD[id];
            float2 D6 = tabD6[id];
            float p1 = fmaf(fd, D.y, D.x);
            float p4 = fmaf(fd, D.w, D.z);
            float p6 = fmaf(fd, D6.y, D6.x);
            sc[r] = p0 * p1;
            float dd = p3 * p4;
            s_dT[warp][b][c] = dd;
            s_dT[warp][c][b] = dd;
            dconf += ((b == c) ? 1.0f : 2.0f) * fabsf(p6 - 0.5f);
            if (b == c) s_p0[warp][b] = p0;
        }
    }
    __syncwarp();

    // ---- sim: 55 items; float4 column reads; dual accumulators ----
#pragma unroll
    for (int r = 0; r < 2; r++) {
        int p = lane + r * 32;
        if (p < NITEM) {
            int b = pb[r], c = pc[r];
            const float4* db4 = (const float4*)&s_dT[warp][b][0];
            const float4* dc4 = (const float4*)&s_dT[warp][c][0];
            const float2* db2 = (const float2*)&s_dT[warp][b][8];
            const float2* dc2 = (const float2*)&s_dT[warp][c][8];
            float4 x0 = db4[0], y0 = dc4[0];
            float4 x1 = db4[1], y1 = dc4[1];
            float2 x2 = db2[0], y2 = dc2[0];
            float pe = plin2r(t2L, fmaf(-16.0f, dav[r], 16.0f));
            float po = plin2r(t2L, fmaf(-16.0f, fabsf(x0.x - y0.x), 16.0f));
            pe *= plin2r(t2L, fmaf(-16.0f, fabsf(x0.y - y0.y), 16.0f));
            po *= plin2r(t2L, fmaf(-16.0f, fabsf(x0.z - y0.z), 16.0f));
            pe *= plin2r(t2L, fmaf(-16.0f, fabsf(x0.w - y0.w), 16.0f));
            po *= plin2r(t2L, fmaf(-16.0f, fabsf(x1.x - y1.x), 16.0f));
            pe *= plin2r(t2L, fmaf(-16.0f, fabsf(x1.y - y1.y), 16.0f));
            po *= plin2r(t2L, fmaf(-16.0f, fabsf(x1.z - y1.z), 16.0f));
            pe *= plin2r(t2L, fmaf(-16.0f, fabsf(x1.w - y1.w), 16.0f));
            po *= plin2r(t2L, fmaf(-16.0f, fabsf(x2.x - y2.x), 16.0f));
            pe *= plin2r(t2L, fmaf(-16.0f, fabsf(x2.y - y2.y), 16.0f));
            float prod = pe * po;
            s_sim[warp][b * OBJ + c] = prod;
            s_sim[warp][c * OBJ + b] = prod;
        }
    }
    __syncwarp();

    // ---- row sims -> reciprocals, correction, aconf ----
    float corr = 0.0f, aconf = 0.0f;
    if (lane < OBJ) {
        float rs = 0.0f;
#pragma unroll
        for (int c = 0; c < OBJ; c++) rs += s_sim[warp][lane * OBJ + c];
        float ri = __fdividef(1.0f, rs);
        s_ri[warp][lane] = ri;
        corr = s_p0[warp][lane] * ri;
        aconf = fabsf(plin2t(tab5, 16.0f * s_att[warp][lane]) - 0.5f);
    }
    __syncwarp();

    // ---- score / all_sims sum (sc held in registers) ----
    float ssum = 0.0f;
#pragma unroll
    for (int r = 0; r < 2; r++) {
        int p = lane + r * 32;
        if (p < NITEM) {
            int b = pb[r], c = pc[r];
            float fac = (b == c) ? 1.0f : 2.0f;
            ssum += fac * sc[r] * s_ri[warp][b] * s_ri[warp][c];
        }
    }

    float tot = sqrtf(warp_sum(ssum + corr) + 1e-20f);
    float confarg = warp_sum(aconf * (1.0f / OBJ) + dconf * (1.0f / (OBJ * OBJ)));
    float conf = plin2t(tab7, 16.0f * confarg);

    // ---- one-hot * conf ----
    float s = fminf(fmaxf(tot, 0.0f), (float)OBJ);
    int ii = (int)s;
    float f = s - (float)ii;
    int oh0 = ii < OBJ ? ii : OBJ;
    int oh1 = (ii + 1) < OBJ ? (ii + 1) : OBJ;
    if (lane < OBJ + 1) {
        float v = 0.0f;
        if (lane == oh0) v += 1.0f - f;
        if (lane == oh1) v += f;
        out[row * (OBJ + 1) + lane] = v * conf;
    }
}

extern "C" void kernel_launch(void* const* d_in, const int* in_sizes, int n_in,
                              void* d_out, int out_size) {
    const float* boxes = (const float*)d_in[0];
    const float* attn  = (const float*)d_in[1];
    const float* ws    = (const float*)d_in[2];
    float* out = (float*)d_out;
    int n = in_sizes[0] / (4 * MOBJ);
    int blocks = (n + WARPS - 1) / WARPS;
    counter_kernel<<<blocks, WARPS * 32>>>(boxes, attn, ws, out, n);
}

// round 14
// speedup vs baseline: 1.0577x; 1.0577x over previous
#include <cuda_runtime.h>
#include <math.h>

#define MOBJ 36
#define OBJ  10
#define NPL  16
#define WARPS 8          // rows per block == warps per block
#define NITEM 55         // upper triangle incl. diagonal of 10x10
#define DPAD 12          // padded dedup column stride (floats)

#define PLMAGIC  12582912.0f   // 1.5 * 2^23
#define PLMAGICI 0x4B400000u

// floor(y) as small int + fractional part, no F2I/I2F/IMIN (y in [0,16]).
__device__ __forceinline__ void plfloor(float y, int& idx, float& f) {
    float z = __fadd_rd(y, PLMAGIC);
    idx = (int)(__float_as_uint(z) - PLMAGICI);
    f = y - (z - PLMAGIC);
}

__device__ __forceinline__ float plin2t(const float2* __restrict__ t, float y) {
    int idx; float f;
    plfloor(y, idx, f);
    float2 v = t[idx];
    return fmaf(f, v.y, v.x);
}

__device__ __forceinline__ float warp_sum(float v) {
#pragma unroll
    for (int o = 16; o; o >>= 1) v += __shfl_xor_sync(0xffffffffu, v, o);
    return v;
}

// monotone map float -> u32 (order preserving), and inverse
__device__ __forceinline__ unsigned mapf(float v) {
    unsigned u = __float_as_uint(v);
    return u ^ ((unsigned)(((int)u) >> 31) | 0x80000000u);
}
__device__ __forceinline__ float unmapf(unsigned m) {
    unsigned u = (m & 0x80000000u) ? (m ^ 0x80000000u) : ~m;
    return __uint_as_float(u);
}

__global__ __launch_bounds__(WARPS * 32)
void counter_kernel(const float* __restrict__ boxes,
                    const float* __restrict__ attn,
                    const float* __restrict__ ws,
                    float* __restrict__ out, int n) {
    __shared__ float4 tabR[NPL + 1];     // {csum0, w0', csum3, w3'}
    __shared__ float4 tabD[NPL + 1];     // {csum1, w1', csum4, w4'}
    __shared__ float2 tabD6[NPL + 1];    // {csum6, w6'}
    __shared__ float2 tab2[NPL + 1], tab5[NPL + 1], tab7[NPL + 1];
    __shared__ unsigned char s_pb[NITEM + 1], s_pc[NITEM + 1];
    __shared__ float4 s_box[WARPS][OBJ];
    __shared__ __align__(16) float s_dT[WARPS][OBJ][DPAD];  // dedup, padded cols
    __shared__ float  s_sim[WARPS][OBJ * OBJ];
    __shared__ float  s_p0[WARPS][OBJ];

    const int tid = threadIdx.x;
    const int warp = tid >> 5, lane = tid & 31;

    // ---- normalize 8 weight sets into packed fused tables ----
    if (tid < 8) {
        float tmp[NPL + 1];
        float s = 0.0f;
#pragma unroll
        for (int k = 0; k <= NPL; k++) { tmp[k] = fabsf(ws[tid * (NPL + 1) + k]); s += tmp[k]; }
        float inv = 1.0f / s;
        float* bp; int st;
        switch (tid) {
            case 0: bp = &tabR[0].x;  st = 4; break;
            case 3: bp = &tabR[0].z;  st = 4; break;
            case 1: bp = &tabD[0].x;  st = 4; break;
            case 4: bp = &tabD[0].z;  st = 4; break;
            case 6: bp = &tabD6[0].x; st = 2; break;
            case 2: bp = &tab2[0].x;  st = 2; break;
            case 5: bp = &tab5[0].x;  st = 2; break;
            default: bp = &tab7[0].x; st = 2; break;
        }
        float c = 0.0f;
#pragma unroll
        for (int k = 0; k <= NPL; k++) {
            c += tmp[k] * inv;
            int k1 = (k + 1) < NPL ? (k + 1) : NPL;
            bp[k * st]     = c;
            bp[k * st + 1] = tmp[k1] * inv;
        }
    }
    // item map p -> (b,c), b <= c
    if (tid < NITEM) {
        int p = tid, b = 0;
        while (p >= OBJ - b) { p -= OBJ - b; b++; }
        s_pb[tid] = (unsigned char)b;
        s_pc[tid] = (unsigned char)(b + p);
    }
    __syncthreads();

    const int row = blockIdx.x * WARPS + warp;
    if (row >= n) return;

    // ---- warp top-10 of 36 via REDUX (exact, low-index tie-break) ----
    unsigned u0 = mapf(attn[row * MOBJ + lane]);
    unsigned u1 = 0;
    if (lane < MOBJ - 32) u1 = mapf(attn[row * MOBJ + 32 + lane]);
    unsigned myval = 0, myidx = 0;
#pragma unroll
    for (int k = 0; k < OBJ; k++) {
        unsigned cand = u0 > u1 ? u0 : u1;
        unsigned m = __reduce_max_sync(0xffffffffu, cand);
        unsigned idx = 0xFFFFFFFFu;
        if (u0 == m) idx = (unsigned)lane;
        if (u1 == m) idx = min(idx, (unsigned)(lane + 32));
        unsigned sel = __reduce_min_sync(0xffffffffu, idx);
        if (sel == (unsigned)lane) u0 = 0;
        else if (sel == (unsigned)(lane + 32)) u1 = 0;
        if (lane == k) { myval = m; myidx = sel; }
    }
    // att lives in registers of lanes 0..9; exchanged by shfl below.
    float a_reg = 0.0f;
    if (lane < OBJ) {
        float v = unmapf(myval);
        a_reg = __fdividef(1.0f, 1.0f + __expf(-v));
        const float* bb = boxes + (size_t)row * 4 * MOBJ + myidx;
        s_box[warp][lane] = make_float4(bb[0], bb[MOBJ], bb[2 * MOBJ], bb[3 * MOBJ]);
    }
    __syncwarp();

    // ---- pair stage: 55 items (b<=c); shared floors, packed tables ----
    float dconf = 0.0f;
    float sc[2], dav[2];
    int pb[2], pc[2];
#pragma unroll
    for (int r = 0; r < 2; r++) {
        int p = lane + r * 32;
        sc[r] = 0.0f; dav[r] = 0.0f; pb[r] = 0; pc[r] = 0;
        int b = 0, c = 0;
        if (p < NITEM) { b = s_pb[p]; c = s_pc[p]; }
        float atb = __shfl_sync(0xffffffffu, a_reg, b);
        float atc = __shfl_sync(0xffffffffu, a_reg, c);
        if (p < NITEM) {
            pb[r] = b; pc[r] = c;
            float4 B = s_box[warp][b], C = s_box[warp][c];
            float iw = fmaxf(fminf(B.z, C.z) - fmaxf(B.x, C.x), 0.0f);
            float ih = fmaxf(fminf(B.w, C.w) - fmaxf(B.y, C.y), 0.0f);
            float inter = iw * ih;
            float aa = fmaxf(B.z - B.x, 0.0f) * fmaxf(B.w - B.y, 0.0f);
            float ab = fmaxf(C.z - C.x, 0.0f) * fmaxf(C.w - C.y, 0.0f);
            float dist = fmaxf(1.0f - __fdividef(inter, aa + ab - inter + 1e-12f), 0.0f);
            float relev = atb * atc;
            dav[r] = fabsf(atb - atc);
            int ir; float fr; plfloor(16.0f * relev, ir, fr);
            float4 R = tabR[ir];
            float p0 = fmaf(fr, R.y, R.x);
            float p3 = fmaf(fr, R.w, R.z);
            int id; float fd; plfloor(16.0f * dist, id, fd);
            float4 D = tabD[id];
            float2 D6 = tabD6[id];
            float p1 = fmaf(fd, D.y, D.x);
            float p4 = fmaf(fd, D.w, D.z);
            float p6 = fmaf(fd, D6.y, D6.x);
            sc[r] = p0 * p1;
            float dd = p3 * p4;
            s_dT[warp][b][c] = dd;
            s_dT[warp][c][b] = dd;
            dconf += ((b == c) ? 1.0f : 2.0f) * fabsf(p6 - 0.5f);
            if (b == c) s_p0[warp][b] = p0;
        }
    }
    __syncwarp();

    // ---- sim: 55 items; float4/float2 column reads; dual accumulators ----
#pragma unroll
    for (int r = 0; r < 2; r++) {
        int p = lane + r * 32;
        if (p < NITEM) {
            int b = pb[r], c = pc[r];
            const float4* db4 = (const float4*)&s_dT[warp][b][0];
            const float4* dc4 = (const float4*)&s_dT[warp][c][0];
            const float2* db2 = (const float2*)&s_dT[warp][b][8];
            const float2* dc2 = (const float2*)&s_dT[warp][c][8];
            float4 x0 = db4[0], y0 = dc4[0];
            float4 x1 = db4[1], y1 = dc4[1];
            float2 x2 = db2[0], y2 = dc2[0];
            float pe = plin2t(tab2, fmaf(-16.0f, dav[r], 16.0f));
            float po = plin2t(tab2, fmaf(-16.0f, fabsf(x0.x - y0.x), 16.0f));
            pe *= plin2t(tab2, fmaf(-16.0f, fabsf(x0.y - y0.y), 16.0f));
            po *= plin2t(tab2, fmaf(-16.0f, fabsf(x0.z - y0.z), 16.0f));
            pe *= plin2t(tab2, fmaf(-16.0f, fabsf(x0.w - y0.w), 16.0f));
            po *= plin2t(tab2, fmaf(-16.0f, fabsf(x1.x - y1.x), 16.0f));
            pe *= plin2t(tab2, fmaf(-16.0f, fabsf(x1.y - y1.y), 16.0f));
            po *= plin2t(tab2, fmaf(-16.0f, fabsf(x1.z - y1.z), 16.0f));
            pe *= plin2t(tab2, fmaf(-16.0f, fabsf(x1.w - y1.w), 16.0f));
            po *= plin2t(tab2, fmaf(-16.0f, fabsf(x2.x - y2.x), 16.0f));
            pe *= plin2t(tab2, fmaf(-16.0f, fabsf(x2.y - y2.y), 16.0f));
            float prod = pe * po;
            s_sim[warp][b * OBJ + c] = prod;
            s_sim[warp][c * OBJ + b] = prod;
        }
    }
    __syncwarp();

    // ---- row sims -> reciprocals (registers), correction, aconf ----
    float corr = 0.0f, aconf = 0.0f, ri_reg = 0.0f;
    if (lane < OBJ) {
        float rs = 0.0f;
#pragma unroll
        for (int c = 0; c < OBJ; c++) rs += s_sim[warp][lane * OBJ + c];
        ri_reg = __fdividef(1.0f, rs);
        corr = s_p0[warp][lane] * ri_reg;
        aconf = fabsf(plin2t(tab5, 16.0f * a_reg) - 0.5f);
    }
    __syncwarp();

    // ---- score / all_sims sum (sc in regs, ri via shfl) ----
    float ssum = 0.0f;
#pragma unroll
    for (int r = 0; r < 2; r++) {
        int p = lane + r * 32;
        float rib = __shfl_sync(0xffffffffu, ri_reg, pb[r]);
        float ric = __shfl_sync(0xffffffffu, ri_reg, pc[r]);
        if (p < NITEM) {
            float fac = (pb[r] == pc[r]) ? 1.0f : 2.0f;
            ssum += fac * sc[r] * rib * ric;
        }
    }

    float tot = sqrtf(warp_sum(ssum + corr) + 1e-20f);
    float confarg = warp_sum(aconf * (1.0f / OBJ) + dconf * (1.0f / (OBJ * OBJ)));
    float conf = plin2t(tab7, 16.0f * confarg);

    // ---- one-hot * conf ----
    float s = fminf(fmaxf(tot, 0.0f), (float)OBJ);
    int ii = (int)s;
    float f = s - (float)ii;
    int oh0 = ii < OBJ ? ii : OBJ;
    int oh1 = (ii + 1) < OBJ ? (ii + 1) : OBJ;
    if (lane < OBJ + 1) {
        float v = 0.0f;
        if (lane == oh0) v += 1.0f - f;
        if (lane == oh1) v += f;
        out[row * (OBJ + 1) + lane] = v * conf;
    }
}

extern "C" void kernel_launch(void* const* d_in, const int* in_sizes, int n_in,
                              void* d_out, int out_size) {
    const float* boxes = (const float*)d_in[0];
    const float* attn  = (const float*)d_in[1];
    const float* ws    = (const float*)d_in[2];
    float* out = (float*)d_out;
    int n = in_sizes[0] / (4 * MOBJ);
    int blocks = (n + WARPS - 1) / WARPS;
    counter_kernel<<<blocks, WARPS * 32>>>(boxes, attn, ws, out, n);
}

// round 15
// speedup vs baseline: 1.1272x; 1.0656x over previous
#include <cuda_runtime.h>
#include <math.h>

#define MOBJ 36
#define OBJ  10
#define NPL  16
#define WARPS 8          // rows per block == warps per block
#define NITEM 55         // upper triangle incl. diagonal of 10x10
#define DPAD 12          // padded dedup column stride (floats)

#define PLMAGIC  12582912.0f   // 1.5 * 2^23
#define PLMAGICI 0x4B400000u

// Shared-memory vector loads at explicit 32-bit shared addresses.
__device__ __forceinline__ float2 lds_v2(unsigned addr) {
    float2 v;
    asm("ld.shared.v2.f32 {%0,%1}, [%2];" : "=f"(v.x), "=f"(v.y) : "r"(addr));
    return v;
}
__device__ __forceinline__ float4 lds_v4(unsigned addr) {
    float4 v;
    asm("ld.shared.v4.f32 {%0,%1,%2,%3}, [%4];"
        : "=f"(v.x), "=f"(v.y), "=f"(v.z), "=f"(v.w) : "r"(addr));
    return v;
}

// Affine piecewise-lin: tables hold (A,B) with A = csum[i] - i*w'[i+1],
// B = w'[i+1], so plin(y) = A[floor(y)] + y*B[floor(y)], y in [0,16].
// cst8 = smem_base - 8*PLMAGICI (mod 2^32): addr = bits(z)*8 + cst8, one IMAD.
__device__ __forceinline__ float plinA(unsigned cst8, float y) {
    float z = __fadd_rd(y, PLMAGIC);
    float2 v = lds_v2(__float_as_uint(z) * 8u + cst8);
    return fmaf(y, v.y, v.x);
}

__device__ __forceinline__ float warp_sum(float v) {
#pragma unroll
    for (int o = 16; o; o >>= 1) v += __shfl_xor_sync(0xffffffffu, v, o);
    return v;
}

// monotone map float -> u32 (order preserving), and inverse
__device__ __forceinline__ unsigned mapf(float v) {
    unsigned u = __float_as_uint(v);
    return u ^ ((unsigned)(((int)u) >> 31) | 0x80000000u);
}
__device__ __forceinline__ float unmapf(unsigned m) {
    unsigned u = (m & 0x80000000u) ? (m ^ 0x80000000u) : ~m;
    return __uint_as_float(u);
}

__global__ __launch_bounds__(WARPS * 32)
void counter_kernel(const float* __restrict__ boxes,
                    const float* __restrict__ attn,
                    const float* __restrict__ ws,
                    float* __restrict__ out, int n) {
    __shared__ float4 tabR[NPL + 1];     // {A0,B0,A3,B3}
    __shared__ float4 tabD[NPL + 1];     // {A1,B1,A4,B4}
    __shared__ float2 tabD6[NPL + 1];    // {A6,B6}
    __shared__ float2 tab2[NPL + 1], tab5[NPL + 1], tab7[NPL + 1];
    __shared__ unsigned char s_pb[NITEM + 1], s_pc[NITEM + 1];
    __shared__ float4 s_box[WARPS][OBJ];
    __shared__ __align__(16) float s_dT[WARPS][OBJ][DPAD];  // dedup, padded cols
    __shared__ float  s_sim[WARPS][OBJ * OBJ];
    __shared__ float  s_p0[WARPS][OBJ];

    const int tid = threadIdx.x;
    const int warp = tid >> 5, lane = tid & 31;

    // ---- normalize 8 weight sets into packed affine tables ----
    if (tid < 8) {
        float tmp[NPL + 1];
        float s = 0.0f;
#pragma unroll
        for (int k = 0; k <= NPL; k++) { tmp[k] = fabsf(ws[tid * (NPL + 1) + k]); s += tmp[k]; }
        float inv = 1.0f / s;
        float* bp; int st;
        switch (tid) {
            case 0: bp = &tabR[0].x;  st = 4; break;
            case 3: bp = &tabR[0].z;  st = 4; break;
            case 1: bp = &tabD[0].x;  st = 4; break;
            case 4: bp = &tabD[0].z;  st = 4; break;
            case 6: bp = &tabD6[0].x; st = 2; break;
            case 2: bp = &tab2[0].x;  st = 2; break;
            case 5: bp = &tab5[0].x;  st = 2; break;
            default: bp = &tab7[0].x; st = 2; break;
        }
        float c = 0.0f;
#pragma unroll
        for (int k = 0; k <= NPL; k++) {
            c += tmp[k] * inv;
            int k1 = (k + 1) < NPL ? (k + 1) : NPL;
            float wn = tmp[k1] * inv;
            bp[k * st]     = c - (float)k * wn;   // A
            bp[k * st + 1] = wn;                  // B
        }
    }
    // item map p -> (b,c), b <= c
    if (tid < NITEM) {
        int p = tid, b = 0;
        while (p >= OBJ - b) { p -= OBJ - b; b++; }
        s_pb[tid] = (unsigned char)b;
        s_pc[tid] = (unsigned char)(b + p);
    }
    __syncthreads();

    // table address constants (one IMAD per lookup)
    const unsigned cst2  = (unsigned)__cvta_generic_to_shared(tab2)  - 8u  * PLMAGICI;
    const unsigned cstR  = (unsigned)__cvta_generic_to_shared(tabR)  - 16u * PLMAGICI;
    const unsigned cstD  = (unsigned)__cvta_generic_to_shared(tabD)  - 16u * PLMAGICI;
    const unsigned cstD6 = (unsigned)__cvta_generic_to_shared(tabD6) - 8u  * PLMAGICI;
    const unsigned cst5  = (unsigned)__cvta_generic_to_shared(tab5)  - 8u  * PLMAGICI;
    const unsigned cst7  = (unsigned)__cvta_generic_to_shared(tab7)  - 8u  * PLMAGICI;

    const int row = blockIdx.x * WARPS + warp;
    if (row >= n) return;

    // ---- warp top-10 of 36 via REDUX (exact, low-index tie-break) ----
    unsigned u0 = mapf(attn[row * MOBJ + lane]);
    unsigned u1 = 0;
    if (lane < MOBJ - 32) u1 = mapf(attn[row * MOBJ + 32 + lane]);
    unsigned myval = 0, myidx = 0;
#pragma unroll
    for (int k = 0; k < OBJ; k++) {
        unsigned cand = u0 > u1 ? u0 : u1;
        unsigned m = __reduce_max_sync(0xffffffffu, cand);
        unsigned idx = 0xFFFFFFFFu;
        if (u0 == m) idx = (unsigned)lane;
        if (u1 == m) idx = min(idx, (unsigned)(lane + 32));
        unsigned sel = __reduce_min_sync(0xffffffffu, idx);
        if (sel == (unsigned)lane) u0 = 0;
        else if (sel == (unsigned)(lane + 32)) u1 = 0;
        if (lane == k) { myval = m; myidx = sel; }
    }
    // a4 = 4*sigmoid(att) in registers of lanes 0..9 (a4b*a4c = 16*relev)
    float a4 = 0.0f;
    if (lane < OBJ) {
        float v = unmapf(myval);
        a4 = __fdividef(4.0f, 1.0f + __expf(-v));
        const float* bb = boxes + (size_t)row * 4 * MOBJ + myidx;
        s_box[warp][lane] = make_float4(bb[0], bb[MOBJ], bb[2 * MOBJ], bb[3 * MOBJ]);
    }
    __syncwarp();

    // ---- pair stage: 55 items (b<=c) ----
    float dconf = 0.0f;
    float sc[2], dav[2];
    int pb[2], pc[2];
#pragma unroll
    for (int r = 0; r < 2; r++) {
        int p = lane + r * 32;
        sc[r] = 0.0f; dav[r] = 0.0f; pb[r] = 0; pc[r] = 0;
        int b = 0, c = 0;
        if (p < NITEM) { b = s_pb[p]; c = s_pc[p]; }
        float a4b = __shfl_sync(0xffffffffu, a4, b);
        float a4c = __shfl_sync(0xffffffffu, a4, c);
        if (p < NITEM) {
            pb[r] = b; pc[r] = c;
            float4 B = s_box[warp][b], C = s_box[warp][c];
            float iw = fmaxf(fminf(B.z, C.z) - fmaxf(B.x, C.x), 0.0f);
            float ih = fmaxf(fminf(B.w, C.w) - fmaxf(B.y, C.y), 0.0f);
            float inter = iw * ih;
            float aa = fmaxf(B.z - B.x, 0.0f) * fmaxf(B.w - B.y, 0.0f);
            float ab = fmaxf(C.z - C.x, 0.0f) * fmaxf(C.w - C.y, 0.0f);
            float q = __fdividef(inter, aa + ab - inter + 1e-12f);
            float yD = fmaxf(fmaf(-16.0f, q, 16.0f), 0.0f);    // 16*dist
            float yR = a4b * a4c;                               // 16*relev
            dav[r] = fabsf(a4b - a4c);                          // 4*|da|
            float4 R = lds_v4(__float_as_uint(__fadd_rd(yR, PLMAGIC)) * 16u + cstR);
            float p0 = fmaf(yR, R.y, R.x);
            float p3 = fmaf(yR, R.w, R.z);
            unsigned zD = __float_as_uint(__fadd_rd(yD, PLMAGIC));
            float4 D = lds_v4(zD * 16u + cstD);
            float2 D6 = lds_v2(zD * 8u + cstD6);
            float p1 = fmaf(yD, D.y, D.x);
            float p4 = fmaf(yD, D.w, D.z);
            float p6 = fmaf(yD, D6.y, D6.x);
            sc[r] = p0 * p1;
            float dd = p3 * p4;
            s_dT[warp][b][c] = dd;
            s_dT[warp][c][b] = dd;
            dconf += ((b == c) ? 1.0f : 2.0f) * fabsf(p6 - 0.5f);
            if (b == c) s_p0[warp][b] = p0;
        }
    }
    __syncwarp();

    // ---- sim: 55 items; vector column reads; dual accumulators ----
#pragma unroll
    for (int r = 0; r < 2; r++) {
        int p = lane + r * 32;
        if (p < NITEM) {
            int b = pb[r], c = pc[r];
            const float4* db4 = (const float4*)&s_dT[warp][b][0];
            const float4* dc4 = (const float4*)&s_dT[warp][c][0];
            const float2* db2 = (const float2*)&s_dT[warp][b][8];
            const float2* dc2 = (const float2*)&s_dT[warp][c][8];
            float4 x0 = db4[0], y0 = dc4[0];
            float4 x1 = db4[1], y1 = dc4[1];
            float2 x2 = db2[0], y2 = dc2[0];
            float pe = plinA(cst2, fmaf(-4.0f, dav[r], 16.0f));
            float po = plinA(cst2, fmaf(-16.0f, fabsf(x0.x - y0.x), 16.0f));
            pe *= plinA(cst2, fmaf(-16.0f, fabsf(x0.y - y0.y), 16.0f));
            po *= plinA(cst2, fmaf(-16.0f, fabsf(x0.z - y0.z), 16.0f));
            pe *= plinA(cst2, fmaf(-16.0f, fabsf(x0.w - y0.w), 16.0f));
            po *= plinA(cst2, fmaf(-16.0f, fabsf(x1.x - y1.x), 16.0f));
            pe *= plinA(cst2, fmaf(-16.0f, fabsf(x1.y - y1.y), 16.0f));
            po *= plinA(cst2, fmaf(-16.0f, fabsf(x1.z - y1.z), 16.0f));
            pe *= plinA(cst2, fmaf(-16.0f, fabsf(x1.w - y1.w), 16.0f));
            po *= plinA(cst2, fmaf(-16.0f, fabsf(x2.x - y2.x), 16.0f));
            pe *= plinA(cst2, fmaf(-16.0f, fabsf(x2.y - y2.y), 16.0f));
            float prod = pe * po;
            s_sim[warp][b * OBJ + c] = prod;
            s_sim[warp][c * OBJ + b] = prod;
        }
    }
    __syncwarp();

    // ---- row sims -> reciprocals (registers), correction, aconf ----
    float corr = 0.0f, aconf = 0.0f, ri_reg = 0.0f;
    if (lane < OBJ) {
        float rs = 0.0f;
#pragma unroll
        for (int c = 0; c < OBJ; c++) rs += s_sim[warp][lane * OBJ + c];
        ri_reg = __fdividef(1.0f, rs);
        corr = s_p0[warp][lane] * ri_reg;
        aconf = fabsf(plinA(cst5, 4.0f * a4) - 0.5f);
    }
    __syncwarp();

    // ---- score / all_sims sum (sc in regs, ri via shfl) ----
    float ssum = 0.0f;
#pragma unroll
    for (int r = 0; r < 2; r++) {
        int p = lane + r * 32;
        float rib = __shfl_sync(0xffffffffu, ri_reg, pb[r]);
        float ric = __shfl_sync(0xffffffffu, ri_reg, pc[r]);
        if (p < NITEM) {
            float fac = (pb[r] == pc[r]) ? 1.0f : 2.0f;
            ssum += fac * sc[r] * rib * ric;
        }
    }

    float tot = sqrtf(warp_sum(ssum + corr) + 1e-20f);
    float confarg = warp_sum(aconf * (1.0f / OBJ) + dconf * (1.0f / (OBJ * OBJ)));
    float conf = plinA(cst7, 16.0f * confarg);

    // ---- one-hot * conf ----
    float s = fminf(fmaxf(tot, 0.0f), (float)OBJ);
    int ii = (int)s;
    float f = s - (float)ii;
    int oh0 = ii < OBJ ? ii : OBJ;
    int oh1 = (ii + 1) < OBJ ? (ii + 1) : OBJ;
    if (lane < OBJ + 1) {
        float v = 0.0f;
        if (lane == oh0) v += 1.0f - f;
        if (lane == oh1) v += f;
        out[row * (OBJ + 1) + lane] = v * conf;
    }
}

extern "C" void kernel_launch(void* const* d_in, const int* in_sizes, int n_in,
                              void* d_out, int out_size) {
    const float* boxes = (const float*)d_in[0];
    const float* attn  = (const float*)d_in[1];
    const float* ws    = (const float*)d_in[2];
    float* out = (float*)d_out;
    int n = in_sizes[0] / (4 * MOBJ);
    int blocks = (n + WARPS - 1) / WARPS;
    counter_kernel<<<blocks, WARPS * 32>>>(boxes, attn, ws, out, n);
}